// round 17
// baseline (speedup 1.0000x reference)
#include <cuda_runtime.h>
#include <cuda_bf16.h>
#include <cuda_fp16.h>
#include <cuda_fp8.h>
#include <math.h>
#include <stdint.h>

// ----------------------------------------------------------------------------
// Problem constants
// ----------------------------------------------------------------------------
#define NS   16384
#define INF_ 1024
#define H_   2048
#define NC   10
#define PRIOR_VAR 100.0

#define SCALE_W   64.0f
#define SCALE_H   8.0f
#define INV_G1    (1.0f / SCALE_W)
#define INV_G2    (1.0f / (SCALE_W * SCALE_H))

#define MBLKS 128             // 128-row blocks for h1/h2 (GEMM BM=128)
#define XBLKS 64              // 256-row blocks for X conversion
#define NT1   (H_ / 128)      // 16 tiles per row block (BN=128)

// grid layout
#define N_CONVX  256          // 64 blocks x 4 CTAs
#define N_CONVW1 32           // 16 blocks x 2 CTAs
#define N_CONVW2 64           // 16 blocks x 4 CTAs
#define BID_SMALL (N_CONVX + N_CONVW1 + N_CONVW2)        // 352
#define BID_G1    (BID_SMALL + 1)                        // 353
#define NG        2048                                   // tiles per GEMM
#define BID_G2    (BID_G1 + NG)                          // 2401
#define BID_LOSS  (BID_G2 + NG)                          // 4449
#define GRID_TOT  (BID_LOSS + 1024)                      // 5473

// ----------------------------------------------------------------------------
// Scratch (static device globals — no allocations allowed)
// ----------------------------------------------------------------------------
__device__ unsigned char g_Xq [NS * INF_];          // 16 MB
__device__ unsigned char g_W1q[H_ * INF_];          //  2 MB
__device__ unsigned char g_W2q[H_ * H_];            //  4 MB
__device__ unsigned char g_h1q[(size_t)NS * H_];    // 32 MB
__device__ __nv_bfloat16 g_h2 [(size_t)NS * H_];    // 64 MB
__device__ int g_cntX [XBLKS];
__device__ int g_cntW1[NT1];
__device__ int g_cntW2[NT1];
__device__ int g_cnt1 [MBLKS];
__device__ int g_cnt2 [MBLKS];

// ----------------------------------------------------------------------------
// PTX helpers
// ----------------------------------------------------------------------------
__device__ __forceinline__ void cp16(uint32_t dst, const void* src) {
    asm volatile("cp.async.cg.shared.global [%0], [%1], 16;" :: "r"(dst), "l"(src));
}
__device__ __forceinline__ void cp_commit() {
    asm volatile("cp.async.commit_group;");
}
template<int N> __device__ __forceinline__ void cp_wait() {
    asm volatile("cp.async.wait_group %0;" :: "n"(N));
}
__device__ __forceinline__ void ldsm_x4(uint32_t* r, uint32_t addr) {
    asm volatile("ldmatrix.sync.aligned.m8n8.x4.shared.b16 {%0,%1,%2,%3}, [%4];"
                 : "=r"(r[0]), "=r"(r[1]), "=r"(r[2]), "=r"(r[3]) : "r"(addr));
}
__device__ __forceinline__ void mma_fp8_h(uint32_t* d, const uint32_t* a,
                                          const uint32_t* b) {
    asm volatile("mma.sync.aligned.m16n8k32.row.col.f16.e4m3.e4m3.f16 "
                 "{%0,%1}, {%2,%3,%4,%5}, {%6,%7}, {%0,%1};"
                 : "+r"(d[0]), "+r"(d[1])
                 : "r"(a[0]), "r"(a[1]), "r"(a[2]), "r"(a[3]),
                   "r"(b[0]), "r"(b[1]));
}
__device__ __forceinline__ unsigned char f2e4m3(float v) {
    return (unsigned char)__nv_cvt_float_to_fp8(v, __NV_SATFINITE, __NV_E4M3);
}
__device__ __forceinline__ uint32_t pack4(float4 v, float s) {
    return (uint32_t)f2e4m3(v.x * s)
         | ((uint32_t)f2e4m3(v.y * s) << 8)
         | ((uint32_t)f2e4m3(v.z * s) << 16)
         | ((uint32_t)f2e4m3(v.w * s) << 24);
}

// spin until *cnt >= target (thread 0), then block-wide fence
__device__ __forceinline__ void wait_cnt(int* cnt, int target) {
    if (threadIdx.x == 0)
        while (atomicAdd(cnt, 0) < target) __nanosleep(64);
    __syncthreads();
    __threadfence();
}
// make this CTA's writes visible, then bump counter
__device__ __forceinline__ void publish(int* cnt) {
    __threadfence();
    __syncthreads();
    if (threadIdx.x == 0) atomicAdd(cnt, 1);
}
// block-reduce s and add -0.5*s/VAR to out
__device__ __forceinline__ void prior_add(float s, float* out) {
    #pragma unroll
    for (int o = 16; o; o >>= 1) s += __shfl_xor_sync(0xFFFFFFFFu, s, o);
    __shared__ float ws[8];
    if ((threadIdx.x & 31) == 0) ws[threadIdx.x >> 5] = s;
    __syncthreads();
    if (threadIdx.x < 8) {
        float t = ws[threadIdx.x];
        #pragma unroll
        for (int o = 4; o; o >>= 1) t += __shfl_xor_sync(0xFFu, t, o);
        if (threadIdx.x == 0) atomicAdd(out, (float)(-0.5 / PRIOR_VAR) * t);
    }
}

// ----------------------------------------------------------------------------
// Mega-kernel. GEMM: CTA 128x128, BK=128, 2 stages, warp tile 32x64,
// EXPLICIT fragment double-buffering (ldsm for ks+1 overlaps mma of ks).
// ----------------------------------------------------------------------------
#define BM 128
#define BN 128
#define BK 128
#define ROWB 144
#define HALF_STG (BM * ROWB)           // 18432
#define STG_BYTES (2 * HALF_STG)       // 36864
#define SMEM_DYN (2 * STG_BYTES)       // 73728; x2 CTAs = 147456

__global__ __launch_bounds__(256, 2)
void mega_kernel(const float* __restrict__ X,
                 const float* __restrict__ W1, const float* __restrict__ b1,
                 const float* __restrict__ W2, const float* __restrict__ b2,
                 const float* __restrict__ W3, const float* __restrict__ b3,
                 const int*   __restrict__ Y,  float* __restrict__ out)
{
    extern __shared__ unsigned char smem[];
    const int bid = blockIdx.x;
    const int tid = threadIdx.x;

    // ---------------- conversion phase (bids 0..352) ----------------
    if (bid < N_CONVX) {
        int blk = bid >> 2, q = bid & 3;
        size_t base4 = (((size_t)blk * 256 + q * 64) * INF_) >> 2;
        const float4* src = (const float4*)X + base4;
        uint32_t* dst = (uint32_t*)g_Xq + base4;
        for (int i = tid; i < 16384; i += 256)
            dst[i] = pack4(src[i], 1.0f);
        publish(&g_cntX[blk]);
        return;
    }
    if (bid < N_CONVX + N_CONVW1) {
        int b2i = bid - N_CONVX, blk = b2i >> 1, hf = b2i & 1;
        size_t base4 = (((size_t)blk * 128 + hf * 64) * INF_) >> 2;
        const float4* src = (const float4*)W1 + base4;
        uint32_t* dst = (uint32_t*)g_W1q + base4;
        float s = 0.f;
        for (int i = tid; i < 16384; i += 256) {
            float4 v = src[i];
            dst[i] = pack4(v, SCALE_W);
            s += v.x * v.x + v.y * v.y + v.z * v.z + v.w * v.w;
        }
        prior_add(s, out);
        publish(&g_cntW1[blk]);
        return;
    }
    if (bid < BID_SMALL) {
        int b2i = bid - (N_CONVX + N_CONVW1), blk = b2i >> 2, q = b2i & 3;
        size_t base4 = (((size_t)blk * 128 + q * 32) * H_) >> 2;
        const float4* src = (const float4*)W2 + base4;
        uint32_t* dst = (uint32_t*)g_W2q + base4;
        float s = 0.f;
        for (int i = tid; i < 16384; i += 256) {
            float4 v = src[i];
            dst[i] = pack4(v, SCALE_W);
            s += v.x * v.x + v.y * v.y + v.z * v.z + v.w * v.w;
        }
        prior_add(s, out);
        publish(&g_cntW2[blk]);
        return;
    }
    if (bid == BID_SMALL) {
        float s = 0.f;
        for (int i = tid; i < H_; i += 256) { float v = b1[i]; s += v * v; }
        for (int i = tid; i < H_; i += 256) { float v = b2[i]; s += v * v; }
        for (int i = tid; i < NC * H_; i += 256) { float v = W3[i]; s += v * v; }
        for (int i = tid; i < NC; i += 256) { float v = b3[i]; s += v * v; }
        prior_add(s, out);
        return;
    }

    // ---------------- loss phase (bids >= BID_LOSS) ----------------
    if (bid >= BID_LOSS) {
        int lb = bid - BID_LOSS;                 // 0..1023, 16 rows each
        __nv_bfloat16* sW = (__nv_bfloat16*)smem;  // 40 KB of dynamic smem
        __shared__ float sSum;
        if (tid == 0) sSum = 0.f;
        for (int i = tid; i < NC * H_ / 2; i += 256) {
            float2 w2 = ((const float2*)W3)[i];
            *(__nv_bfloat162*)(sW + 2 * i) = __floats2bfloat162_rn(w2.x, w2.y);
        }
        wait_cnt(&g_cnt2[lb >> 3], NT1);         // 128-row block of h2
        const int lane = tid & 31, warp = tid >> 5;
        float local = 0.f;
        #pragma unroll
        for (int rr = 0; rr < 2; rr++) {
            int row = lb * 16 + warp * 2 + rr;
            const __nv_bfloat16* hr = g_h2 + (size_t)row * H_;
            float acc[NC];
            #pragma unroll
            for (int c = 0; c < NC; c++) acc[c] = 0.f;
            #pragma unroll 4
            for (int i = 0; i < H_ / 128; i++) {
                int k = i * 128 + lane * 4;
                uint2 hp = *(const uint2*)(hr + k);
                float2 ha = __bfloat1622float2(*(const __nv_bfloat162*)&hp.x);
                float2 hb = __bfloat1622float2(*(const __nv_bfloat162*)&hp.y);
                #pragma unroll
                for (int c = 0; c < NC; c++) {
                    uint2 wp = *(const uint2*)(sW + c * H_ + k);
                    float2 wa = __bfloat1622float2(*(const __nv_bfloat162*)&wp.x);
                    float2 wb = __bfloat1622float2(*(const __nv_bfloat162*)&wp.y);
                    acc[c] += ha.x * wa.x + ha.y * wa.y + hb.x * wb.x + hb.y * wb.y;
                }
            }
            #pragma unroll
            for (int c = 0; c < NC; c++) {
                #pragma unroll
                for (int o = 16; o; o >>= 1)
                    acc[c] += __shfl_xor_sync(0xFFFFFFFFu, acc[c], o);
            }
            if (lane == 0) {
                float lg[NC];
                float m = -1e30f;
                #pragma unroll
                for (int c = 0; c < NC; c++) {
                    lg[c] = acc[c] + b3[c];
                    m = fmaxf(m, lg[c]);
                }
                float se = 0.f;
                #pragma unroll
                for (int c = 0; c < NC; c++) se += expf(lg[c] - m);
                local += lg[Y[row]] - (m + logf(se));
            }
        }
        if (lane == 0) atomicAdd(&sSum, local);
        __syncthreads();
        if (tid == 0) atomicAdd(out, sSum);
        return;
    }

    // ---------------- GEMM phase ----------------
    const int which = (bid < BID_G2) ? 0 : 1;
    const int t     = which ? (bid - BID_G2) : (bid - BID_G1);
    const int bnIdx = t & 15;
    const int bmIdx = t >> 4;           // 0..127
    const int bm    = bmIdx * BM;
    const int bn    = bnIdx * BN;
    const int K     = which ? H_ : INF_;
    const float* bias = which ? b2 : b1;
    const unsigned char* __restrict__ A = which ? g_h1q : g_Xq;
    const unsigned char* __restrict__ B = which ? g_W2q : g_W1q;

    if (which) {
        if (tid == 0) {
            while (atomicAdd(&g_cnt1[bmIdx], 0) < NT1) __nanosleep(64);
            while (atomicAdd(&g_cntW2[bnIdx], 0) < 4)  __nanosleep(64);
        }
        __syncthreads();
        __threadfence();
    } else {
        if (tid == 0) {
            while (atomicAdd(&g_cntX[bmIdx >> 1], 0) < 4) __nanosleep(64);
            while (atomicAdd(&g_cntW1[bnIdx], 0) < 2)     __nanosleep(64);
        }
        __syncthreads();
        __threadfence();
    }

    uint32_t sb;
    asm("{ .reg .u64 t; cvta.to.shared.u64 t, %1; cvt.u32.u64 %0, t; }"
        : "=r"(sb) : "l"(smem));

    const int lane = tid & 31;
    const int warp = tid >> 5;
    const int wm   = warp >> 1;
    const int wn   = warp & 1;

    uint32_t acc[2][8][2];   // 32 regs
    #pragma unroll
    for (int i = 0; i < 2; i++)
        #pragma unroll
        for (int j = 0; j < 8; j++) { acc[i][j][0] = 0u; acc[i][j][1] = 0u; }

    const int KT = K / BK;

    // one stage: A 128 rows x 128B + B 128 rows x 128B = 2048 x 16B chunks
    auto load_stage = [&](int st, int kt) {
        uint32_t aB = sb + st * STG_BYTES;
        uint32_t bB = aB + HALF_STG;
        const unsigned char* Ap = A + (size_t)bm * K + kt * BK;
        const unsigned char* Bp = B + (size_t)bn * K + kt * BK;
        #pragma unroll
        for (int q = 0; q < 4; q++) {
            int idx = tid + q * 256;
            int r = idx >> 3, c = (idx & 7) * 16;
            cp16(aB + r * ROWB + c, Ap + (size_t)r * K + c);
            cp16(bB + r * ROWB + c, Bp + (size_t)r * K + c);
        }
    };

    load_stage(0, 0);
    cp_commit();

    const int aRow = wm * 32 + (lane & 15);
    const uint32_t aOff0 = (uint32_t)(aRow * ROWB + (lane >> 4) * 16);
    const uint32_t aOff1 = (uint32_t)((aRow + 16) * ROWB + (lane >> 4) * 16);
    const int bRow = wn * 64 + ((lane >> 4) & 1) * 8 + (lane & 7);
    const uint32_t bOffBase = (uint32_t)(bRow * ROWB + ((lane >> 3) & 1) * 16);

    // double-buffered fragments (explicit software pipeline)
    uint32_t aF[2][2][4];   // [buf][mi][4]
    uint32_t bF[2][4][4];   // [buf][njp][4]

    auto ld_frags = [&](int f, uint32_t aBase, uint32_t bBase, int ks) {
        ldsm_x4(aF[f][0], aBase + ks * 32 + aOff0);
        ldsm_x4(aF[f][1], aBase + ks * 32 + aOff1);
        #pragma unroll
        for (int njp = 0; njp < 4; njp++)
            ldsm_x4(bF[f][njp], bBase + ks * 32 + bOffBase + njp * 16 * ROWB);
    };
    auto do_mma = [&](int f) {
        #pragma unroll
        for (int njp = 0; njp < 4; njp++) {
            #pragma unroll
            for (int h = 0; h < 2; h++) {
                mma_fp8_h(acc[0][njp * 2 + h], aF[f][0], &bF[f][njp][2 * h]);
                mma_fp8_h(acc[1][njp * 2 + h], aF[f][1], &bF[f][njp][2 * h]);
            }
        }
    };

    for (int i = 0; i < KT; i++) {
        const int s = i & 1;
        cp_wait<0>();
        __syncthreads();
        if (i + 1 < KT) load_stage(s ^ 1, i + 1);
        cp_commit();

        const uint32_t aBase = sb + s * STG_BYTES;
        const uint32_t bBase = aBase + HALF_STG;

        ld_frags(0, aBase, bBase, 0);
        #pragma unroll
        for (int ks = 0; ks < 4; ks++) {
            int cur = ks & 1;
            if (ks < 3) ld_frags(cur ^ 1, aBase, bBase, ks + 1);
            do_mma(cur);
        }
    }

    // epilogue
    const float inv = which ? INV_G2 : INV_G1;
    #pragma unroll
    for (int mi = 0; mi < 2; mi++) {
        int row0 = bm + wm * 32 + mi * 16 + (lane >> 2);
        #pragma unroll
        for (int nj = 0; nj < 8; nj++) {
            int col = bn + wn * 64 + nj * 8 + 2 * (lane & 3);
            float bv0 = __ldg(bias + col), bv1 = __ldg(bias + col + 1);
            float2 f01 = __half22float2(*(const __half2*)&acc[mi][nj][0]);
            float2 f23 = __half22float2(*(const __half2*)&acc[mi][nj][1]);
            float v0 = fmaxf(f01.x * inv + bv0, 0.f);
            float v1 = fmaxf(f01.y * inv + bv1, 0.f);
            float v2 = fmaxf(f23.x * inv + bv0, 0.f);
            float v3 = fmaxf(f23.y * inv + bv1, 0.f);
            if (which == 0) {
                unsigned short p0 = (unsigned short)f2e4m3(v0 * SCALE_H) |
                                    ((unsigned short)f2e4m3(v1 * SCALE_H) << 8);
                unsigned short p1 = (unsigned short)f2e4m3(v2 * SCALE_H) |
                                    ((unsigned short)f2e4m3(v3 * SCALE_H) << 8);
                *(unsigned short*)(g_h1q + (size_t)row0 * H_ + col)       = p0;
                *(unsigned short*)(g_h1q + (size_t)(row0 + 8) * H_ + col) = p1;
            } else {
                *(__nv_bfloat162*)(g_h2 + (size_t)row0 * H_ + col) =
                    __floats2bfloat162_rn(v0, v1);
                *(__nv_bfloat162*)(g_h2 + (size_t)(row0 + 8) * H_ + col) =
                    __floats2bfloat162_rn(v2, v3);
            }
        }
    }

    publish(which ? &g_cnt2[bmIdx] : &g_cnt1[bmIdx]);
}

// ----------------------------------------------------------------------------
// init: prior constant + zero ALL counters (every graph replay).
// ----------------------------------------------------------------------------
__global__ void init_kernel(float* out, float c) {
    int t = threadIdx.x;
    if (t == 0) out[0] = c;
    if (t < MBLKS) { g_cnt1[t] = 0; g_cnt2[t] = 0; }
    if (t < XBLKS) g_cntX[t] = 0;
    if (t < NT1)   { g_cntW1[t] = 0; g_cntW2[t] = 0; }
}

// ----------------------------------------------------------------------------
// kernel_launch  (2 launches)
// ----------------------------------------------------------------------------
extern "C" void kernel_launch(void* const* d_in, const int* in_sizes, int n_in,
                              void* d_out, int out_size)
{
    const float* X  = (const float*)d_in[0];
    const int*   Y  = (const int*)  d_in[1];
    const float* W1 = (const float*)d_in[2];
    const float* b1 = (const float*)d_in[3];
    const float* W2 = (const float*)d_in[4];
    const float* b2 = (const float*)d_in[5];
    const float* W3 = (const float*)d_in[6];
    const float* b3 = (const float*)d_in[7];
    float* out = (float*)d_out;

    cudaFuncSetAttribute(mega_kernel,
                         cudaFuncAttributeMaxDynamicSharedMemorySize, SMEM_DYN);

    double d = 0.0;
    for (int i = 2; i < 8; i++) d += (double)in_sizes[i];
    float cterm = (float)(-0.5 * d * log(2.0 * M_PI * PRIOR_VAR));
    init_kernel<<<1, 128>>>(out, cterm);                                // 0

    mega_kernel<<<GRID_TOT, 256, SMEM_DYN>>>(X, W1, b1, W2, b2,
                                             W3, b3, Y, out);           // 1
}